// round 16
// baseline (speedup 1.0000x reference)
#include <cuda_runtime.h>
#include <cuda_fp16.h>
#include <math.h>

typedef unsigned int u32;
typedef unsigned long long u64;

#define NLEV 16
#define HSIZE (1u << 19)
#define HMASK (HSIZE - 1u)
#define NPTS (4096 * 128)

struct Consts { float res[NLEV]; };

// ---------------- smem byte offsets (all 16B aligned) ----------------
#define SB_WSUM   0        // 4 f32
#define SB_W3T    16       // rgb_w3^T [3][64] f32 = 768
#define SB_WOUT0  784      // w_out col 0 [64] f32 = 256
#define SB_DEN    1040     // density [128] f32 = 512
#define SB_WGT    1552     // volrend weight [128] f32 = 512
#define SB_ACT    2064     // activations fp16: 128 rows x 64k, stride 144B
#define SB_WB1    20496    // w_in^T   [64n][32k] fp16, stride 80B
#define SB_WB2    25616    // w_out^T  [16n][64k] fp16, stride 144B
#define SB_WB3    27920    // rgb_w1^T [64n][16k] fp16, stride 48B
#define SB_WB4    30992    // rgb_w2^T [64n][64k] fp16, stride 144B
#define SMEM_BYTES 40208

__device__ __forceinline__ u32 smem_u32(const void* p) {
    u32 a;
    asm("{ .reg .u64 t; cvta.to.shared.u64 t, %1; cvt.u32.u64 %0, t; }"
        : "=r"(a) : "l"(p));
    return a;
}
__device__ __forceinline__ void ldsm_x4(u32 a[4], u32 addr) {
    asm volatile("ldmatrix.sync.aligned.m8n8.x4.shared.b16 {%0,%1,%2,%3}, [%4];"
                 : "=r"(a[0]), "=r"(a[1]), "=r"(a[2]), "=r"(a[3]) : "r"(addr));
}
__device__ __forceinline__ void ldsm_x2(u32 b[2], u32 addr) {
    asm volatile("ldmatrix.sync.aligned.m8n8.x2.shared.b16 {%0,%1}, [%2];"
                 : "=r"(b[0]), "=r"(b[1]) : "r"(addr));
}
__device__ __forceinline__ void mma16816(float d[4], const u32 a[4], const u32 b[2]) {
    asm volatile("mma.sync.aligned.m16n8k16.row.col.f32.f16.f16.f32 "
                 "{%0,%1,%2,%3},{%4,%5,%6,%7},{%8,%9},{%0,%1,%2,%3};"
                 : "+f"(d[0]), "+f"(d[1]), "+f"(d[2]), "+f"(d[3])
                 : "r"(a[0]), "r"(a[1]), "r"(a[2]), "r"(a[3]),
                   "r"(b[0]), "r"(b[1]));
}

// A fragment addresses (row-major ACT, stride 144B)
__device__ __forceinline__ u32 a_addr(u32 actb, int R, int mt, int ks, int lane) {
    const int sub = lane >> 3, r = lane & 7;
    return actb + (u32)((R + mt * 16 + ((sub & 1) << 3) + r) * 144
                        + ks * 32 + ((sub >> 1) << 4));
}
// B fragment addresses (col-major B == w^T stored [n][k], k-contiguous)
__device__ __forceinline__ u32 b_addr(u32 wb, int strideB, int nt, int ks, int lane) {
    const int sub = (lane >> 3) & 1, r = lane & 7;
    return wb + (u32)((nt * 8 + r) * strideB + ks * 32 + (sub << 4));
}

__device__ __forceinline__ void level_fetch(
    float px, float py, float pz, float r,
    const float2* __restrict__ tab,
    float2 tv[8], float& ax, float& ay, float& az)
{
    const float X = px * r, Y = py * r, Z = pz * r;
    const float fx = floorf(X), fy = floorf(Y), fz = floorf(Z);
    ax = X - fx; ay = Y - fy; az = Z - fz;
    const u32 ix = (u32)fx, iy = (u32)fy, iz = (u32)fz;
    const u32 hx0 = ix, hx1 = ix + 1u;
    const u32 hy0 = iy * 2654435761u, hy1 = hy0 + 2654435761u;
    const u32 hz0 = iz * 805459861u,  hz1 = hz0 + 805459861u;
    #pragma unroll
    for (int c = 0; c < 8; c++) {
        const u32 hx = (c & 4) ? hx1 : hx0;
        const u32 hy = (c & 2) ? hy1 : hy0;
        const u32 hz = (c & 1) ? hz1 : hz0;
        tv[c] = __ldg(tab + ((hx ^ hy ^ hz) & HMASK));
    }
}

__global__ void __launch_bounds__(128, 5) fused_hmma_kernel(
    const float* __restrict__ xyz, const float* __restrict__ delta,
    const float* __restrict__ table,
    const float* __restrict__ w_in, const float* __restrict__ w_out,
    const float* __restrict__ rw1, const float* __restrict__ rw2,
    const float* __restrict__ rw3, float4* __restrict__ out, Consts cc,
    float offset)
{
    extern __shared__ char smem[];
    float* dsf = (float*)smem;
    const u32 sbase = smem_u32(smem);
    const u32 actb = sbase + SB_ACT;
    const int t = threadIdx.x;
    const int lane = t & 31, wid = t >> 5;
    const int g = lane >> 2, t4 = lane & 3;
    const int R = wid * 32;

    // ---------------- prologue: stage fp16 transposed weights ----------------
    {
        half* wb1 = (half*)(smem + SB_WB1);
        half* wb2 = (half*)(smem + SB_WB2);
        half* wb3 = (half*)(smem + SB_WB3);
        half* wb4 = (half*)(smem + SB_WB4);
        for (int i = t; i < 64 * 32; i += 128) {          // WB1[n][k] = w_in[k][n]
            const int n = i >> 5, k = i & 31;
            wb1[n * 40 + k] = __float2half_rn(w_in[k * 64 + n]);
        }
        for (int i = t; i < 16 * 64; i += 128) {          // WB2[n][k] = w_out[k][n]
            const int n = i >> 6, k = i & 63;
            wb2[n * 72 + k] = __float2half_rn(w_out[k * 16 + n]);
        }
        for (int i = t; i < 64 * 16; i += 128) {          // WB3[n][k] = rgb_w1[k][n], k15=0
            const int n = i >> 4, k = i & 15;
            wb3[n * 24 + k] = (k < 15) ? __float2half_rn(rw1[k * 64 + n]) : __half(0.f);
        }
        for (int i = t; i < 64 * 64; i += 128) {          // WB4[n][k] = rgb_w2[k][n]
            const int n = i >> 6, k = i & 63;
            wb4[n * 72 + k] = __float2half_rn(rw2[k * 64 + n]);
        }
        if (t < 64) {
            #pragma unroll
            for (int c = 0; c < 3; c++)
                dsf[SB_W3T / 4 + c * 64 + t] = rw3[t * 3 + c];   // w3^T [c][n]
            dsf[SB_WOUT0 / 4 + t] = w_out[t * 16];               // w_out col 0 (fp32)
        }
    }
    __syncthreads();

    // ---------------- phase 1: encode point t -> ACT row t (fp16) -----------
    const int p = blockIdx.x * 128 + t;
    {
        const float px = __ldg(xyz + 3 * p);
        const float py = __ldg(xyz + 3 * p + 1);
        const float pz = __ldg(xyz + 3 * p + 2);
        float2 tvb[2][8];
        float fr[2][3];
        level_fetch(px, py, pz, cc.res[0], (const float2*)table,
                    tvb[0], fr[0][0], fr[0][1], fr[0][2]);
        #pragma unroll 2
        for (int l = 0; l < NLEV; l++) {
            const int cur = l & 1, nxt = cur ^ 1;
            if (l + 1 < NLEV)
                level_fetch(px, py, pz, cc.res[l + 1],
                            (const float2*)table + (size_t)(l + 1) * HSIZE,
                            tvb[nxt], fr[nxt][0], fr[nxt][1], fr[nxt][2]);
            const float ax = fr[cur][0], ay = fr[cur][1], az = fr[cur][2];
            const float bx = 1.f - ax, by = 1.f - ay, bz = 1.f - az;
            float a0 = 0.f, a1 = 0.f;
            #pragma unroll
            for (int c = 0; c < 8; c++) {
                const float w = ((c & 4) ? ax : bx) * ((c & 2) ? ay : by) * ((c & 1) ? az : bz);
                a0 = fmaf(w, tvb[cur][c].x, a0);
                a1 = fmaf(w, tvb[cur][c].y, a1);
            }
            __half2 hv = __floats2half2_rn(a0, a1);
            *(u32*)(smem + SB_ACT + t * 144 + l * 4) = *(u32*)&hv;
        }
    }
    __syncwarp();   // warp w's rows [R,R+32) complete; GEMMs are warp-private

    // ---------------- GEMM1: h = enc @ w_in  (M32/warp, N64, K32) -----------
    float accH[2][8][4];
    #pragma unroll
    for (int i = 0; i < 2; i++)
        #pragma unroll
        for (int j = 0; j < 8; j++)
            #pragma unroll
            for (int q = 0; q < 4; q++) accH[i][j][q] = 0.f;
    #pragma unroll
    for (int ks = 0; ks < 2; ks++) {
        u32 a0[4], a1[4];
        ldsm_x4(a0, a_addr(actb, R, 0, ks, lane));
        ldsm_x4(a1, a_addr(actb, R, 1, ks, lane));
        #pragma unroll
        for (int nt = 0; nt < 8; nt++) {
            u32 b[2];
            ldsm_x2(b, b_addr(sbase + SB_WB1, 80, nt, ks, lane));
            mma16816(accH[0][nt], a0, b);
            mma16816(accH[1][nt], a1, b);
        }
    }

    // density (raw col 0) scalar fp32 from h fragments + w_out col 0
    {
        float pd[2][2] = {{0.f, 0.f}, {0.f, 0.f}};
        #pragma unroll
        for (int mt = 0; mt < 2; mt++)
            #pragma unroll
            for (int nt = 0; nt < 8; nt++) {
                const int c0 = nt * 8 + 2 * t4;
                const float w0 = dsf[SB_WOUT0 / 4 + c0];
                const float w1 = dsf[SB_WOUT0 / 4 + c0 + 1];
                pd[mt][0] += fmaxf(accH[mt][nt][0], 0.f) * w0 + fmaxf(accH[mt][nt][1], 0.f) * w1;
                pd[mt][1] += fmaxf(accH[mt][nt][2], 0.f) * w0 + fmaxf(accH[mt][nt][3], 0.f) * w1;
            }
        #pragma unroll
        for (int mt = 0; mt < 2; mt++)
            #pragma unroll
            for (int j = 0; j < 2; j++) {
                pd[mt][j] += __shfl_xor_sync(0xffffffffu, pd[mt][j], 1);
                pd[mt][j] += __shfl_xor_sync(0xffffffffu, pd[mt][j], 2);
            }
        if (t4 == 0) {
            #pragma unroll
            for (int mt = 0; mt < 2; mt++) {
                const int row = R + mt * 16 + g;
                dsf[SB_DEN / 4 + row] = pd[mt][0];
                dsf[SB_DEN / 4 + row + 8] = pd[mt][1];
            }
        }
    }

    // relu(h) -> fp16 -> ACT (cols 0..63)
    #pragma unroll
    for (int mt = 0; mt < 2; mt++)
        #pragma unroll
        for (int nt = 0; nt < 8; nt++) {
            const int row = R + mt * 16 + g;
            const int cb = (nt * 8 + 2 * t4) * 2;
            __half2 x = __floats2half2_rn(fmaxf(accH[mt][nt][0], 0.f),
                                          fmaxf(accH[mt][nt][1], 0.f));
            *(u32*)(smem + SB_ACT + row * 144 + cb) = *(u32*)&x;
            __half2 y = __floats2half2_rn(fmaxf(accH[mt][nt][2], 0.f),
                                          fmaxf(accH[mt][nt][3], 0.f));
            *(u32*)(smem + SB_ACT + (row + 8) * 144 + cb) = *(u32*)&y;
        }
    __syncwarp();

    // ---------------- GEMM2: raw = relu(h) @ w_out  (N16, K64) --------------
    // feats (raw[1..15]) stored DIRECTLY as fp16 into ACT cols 0..14.
    // Safe: all GEMM2 ldmatrix reads of ACT complete (warp program order)
    // before these stores; rows are warp-private.
    {
        float acc2[2][2][4];
        #pragma unroll
        for (int i = 0; i < 2; i++)
            #pragma unroll
            for (int j = 0; j < 2; j++)
                #pragma unroll
                for (int q = 0; q < 4; q++) acc2[i][j][q] = 0.f;
        #pragma unroll
        for (int ks = 0; ks < 4; ks++) {
            u32 a0[4], a1[4];
            ldsm_x4(a0, a_addr(actb, R, 0, ks, lane));
            ldsm_x4(a1, a_addr(actb, R, 1, ks, lane));
            #pragma unroll
            for (int nt = 0; nt < 2; nt++) {
                u32 b[2];
                ldsm_x2(b, b_addr(sbase + SB_WB2, 144, nt, ks, lane));
                mma16816(acc2[0][nt], a0, b);
                mma16816(acc2[1][nt], a1, b);
            }
        }
        #pragma unroll
        for (int mt = 0; mt < 2; mt++)
            #pragma unroll
            for (int nt = 0; nt < 2; nt++) {
                const int row0 = R + mt * 16 + g;
                const int row1 = row0 + 8;
                const int c = nt * 8 + 2 * t4;    // even; pair (c, c+1)
                // col c: feat slot c-1 (skip density col 0 — fp32 path owns it)
                if (c > 0) {
                    *(half*)(smem + SB_ACT + row0 * 144 + (c - 1) * 2) =
                        __float2half_rn(acc2[mt][nt][0]);
                    *(half*)(smem + SB_ACT + row1 * 144 + (c - 1) * 2) =
                        __float2half_rn(acc2[mt][nt][2]);
                }
                // col c+1: feat slot c
                *(half*)(smem + SB_ACT + row0 * 144 + c * 2) =
                    __float2half_rn(acc2[mt][nt][1]);
                *(half*)(smem + SB_ACT + row1 * 144 + c * 2) =
                    __float2half_rn(acc2[mt][nt][3]);
            }
    }
    // zero K-pad col 15 of own row
    *(half*)(smem + SB_ACT + t * 144 + 15 * 2) = __half(0.f);
    __syncwarp();

    // ---------------- volrend: block scan over density -----------------------
    {
        __syncthreads();   // DEN rows written per-warp; scan needs all 128
        const float d0raw = dsf[SB_DEN / 4 + t];
        const float dd = expf(d0raw + offset + logf(__ldg(delta + p)));
        float s = dd;
        #pragma unroll
        for (int o = 1; o < 32; o <<= 1) {
            const float v = __shfl_up_sync(0xffffffffu, s, o);
            if (lane >= o) s += v;
        }
        if (lane == 31) dsf[SB_WSUM / 4 + wid] = s;
        __syncthreads();
        float pref = 0.f;
        #pragma unroll
        for (int w = 0; w < 3; w++)
            if (wid > w) pref += dsf[SB_WSUM / 4 + w];
        const float wgt = (1.f - expf(-dd)) * expf(-(pref + s - dd));
        dsf[SB_WGT / 4 + t] = wgt;
    }
    __syncwarp();

    // ---------------- GEMM3: h1 = feats @ rgb_w1  (N64, K16) ----------------
    #pragma unroll
    for (int i = 0; i < 2; i++)
        #pragma unroll
        for (int j = 0; j < 8; j++)
            #pragma unroll
            for (int q = 0; q < 4; q++) accH[i][j][q] = 0.f;
    {
        u32 a0[4], a1[4];
        ldsm_x4(a0, a_addr(actb, R, 0, 0, lane));
        ldsm_x4(a1, a_addr(actb, R, 1, 0, lane));
        #pragma unroll
        for (int nt = 0; nt < 8; nt++) {
            u32 b[2];
            ldsm_x2(b, b_addr(sbase + SB_WB3, 48, nt, 0, lane));
            mma16816(accH[0][nt], a0, b);
            mma16816(accH[1][nt], a1, b);
        }
    }
    // relu(h1) -> fp16 -> ACT cols 0..63
    #pragma unroll
    for (int mt = 0; mt < 2; mt++)
        #pragma unroll
        for (int nt = 0; nt < 8; nt++) {
            const int row = R + mt * 16 + g;
            const int cb = (nt * 8 + 2 * t4) * 2;
            __half2 x = __floats2half2_rn(fmaxf(accH[mt][nt][0], 0.f),
                                          fmaxf(accH[mt][nt][1], 0.f));
            *(u32*)(smem + SB_ACT + row * 144 + cb) = *(u32*)&x;
            __half2 y = __floats2half2_rn(fmaxf(accH[mt][nt][2], 0.f),
                                          fmaxf(accH[mt][nt][3], 0.f));
            *(u32*)(smem + SB_ACT + (row + 8) * 144 + cb) = *(u32*)&y;
        }
    __syncwarp();

    // ---------------- GEMM4: h2 = relu(h1) @ rgb_w2  (N64, K64) -------------
    #pragma unroll
    for (int i = 0; i < 2; i++)
        #pragma unroll
        for (int j = 0; j < 8; j++)
            #pragma unroll
            for (int q = 0; q < 4; q++) accH[i][j][q] = 0.f;
    #pragma unroll
    for (int ks = 0; ks < 4; ks++) {
        u32 a0[4], a1[4];
        ldsm_x4(a0, a_addr(actb, R, 0, ks, lane));
        ldsm_x4(a1, a_addr(actb, R, 1, ks, lane));
        #pragma unroll
        for (int nt = 0; nt < 8; nt++) {
            u32 b[2];
            ldsm_x2(b, b_addr(sbase + SB_WB4, 144, nt, ks, lane));
            mma16816(accH[0][nt], a0, b);
            mma16816(accH[1][nt], a1, b);
        }
    }

    // ---------------- rgb = sigmoid(relu(h2) @ rgb_w3) -----------------------
    #pragma unroll
    for (int mt = 0; mt < 2; mt++) {
        float pr0[3] = {0.f, 0.f, 0.f};
        float pr1[3] = {0.f, 0.f, 0.f};
        #pragma unroll
        for (int nt = 0; nt < 8; nt++) {
            const int c0 = nt * 8 + 2 * t4;
            const float v0 = fmaxf(accH[mt][nt][0], 0.f);
            const float v1 = fmaxf(accH[mt][nt][1], 0.f);
            const float v2 = fmaxf(accH[mt][nt][2], 0.f);
            const float v3 = fmaxf(accH[mt][nt][3], 0.f);
            #pragma unroll
            for (int c = 0; c < 3; c++) {
                const float2 wv = *(const float2*)&dsf[SB_W3T / 4 + c * 64 + c0];
                pr0[c] += v0 * wv.x + v1 * wv.y;
                pr1[c] += v2 * wv.x + v3 * wv.y;
            }
        }
        #pragma unroll
        for (int c = 0; c < 3; c++) {
            pr0[c] += __shfl_xor_sync(0xffffffffu, pr0[c], 1);
            pr0[c] += __shfl_xor_sync(0xffffffffu, pr0[c], 2);
            pr1[c] += __shfl_xor_sync(0xffffffffu, pr1[c], 1);
            pr1[c] += __shfl_xor_sync(0xffffffffu, pr1[c], 2);
        }
        if (t4 == 0) {
            const int row0 = R + mt * 16 + g;
            const float wg0 = dsf[SB_WGT / 4 + row0];
            out[blockIdx.x * 128 + row0] = make_float4(
                wg0, 1.f / (1.f + expf(-pr0[0])),
                1.f / (1.f + expf(-pr0[1])), 1.f / (1.f + expf(-pr0[2])));
            const int row1 = row0 + 8;
            const float wg1 = dsf[SB_WGT / 4 + row1];
            out[blockIdx.x * 128 + row1] = make_float4(
                wg1, 1.f / (1.f + expf(-pr1[0])),
                1.f / (1.f + expf(-pr1[1])), 1.f / (1.f + expf(-pr1[2])));
        }
    }
}

extern "C" void kernel_launch(void* const* d_in, const int* in_sizes, int n_in,
                              void* d_out, int out_size)
{
    const float* xyz   = (const float*)d_in[0];
    const float* delta = (const float*)d_in[1];
    const float* table = (const float*)d_in[2];
    const float* w_in  = (const float*)d_in[3];
    const float* w_out = (const float*)d_in[4];
    const float* rw1   = (const float*)d_in[5];
    const float* rw2   = (const float*)d_in[6];
    const float* rw3   = (const float*)d_in[7];
    float4* out = (float4*)d_out;

    Consts cc;
    const double scale = exp((log(4096.0) - log(16.0)) / 15.0);
    for (int l = 0; l < NLEV; l++)
        cc.res[l] = (float)floor(16.0 * pow(scale, (double)l));
    const float offset = (float)(log(log(1.0 / 0.99)) - log(6.0 - 2.0) - 0.5);

    static int inited = 0;
    if (!inited) {
        cudaFuncSetAttribute(fused_hmma_kernel,
                             cudaFuncAttributeMaxDynamicSharedMemorySize,
                             SMEM_BYTES);
        inited = 1;
    }

    fused_hmma_kernel<<<4096, 128, SMEM_BYTES>>>(
        xyz, delta, table, w_in, w_out, rw1, rw2, rw3, out, cc, offset);
}

// round 17
// speedup vs baseline: 1.5162x; 1.5162x over previous
#include <cuda_runtime.h>
#include <cuda_fp16.h>
#include <math.h>

typedef unsigned int u32;
typedef unsigned long long u64;

#define NLEV 16
#define HSIZE (1u << 19)
#define HMASK (HSIZE - 1u)
#define NPTS (4096 * 128)

struct Consts { float res[NLEV]; };

// ---------------- smem byte offsets (all 16B aligned) ----------------
#define SB_WSUM   0        // 4 f32
#define SB_W3T    16       // rgb_w3^T [3][64] f32 = 768
#define SB_WOUT0  784      // w_out col 0 [64] f32 = 256
#define SB_ACT    1040     // activations fp16: 128 rows x 64k, stride 144B
#define SB_RAW    19472    // raw f32: 128 rows x 18, stride 72B (c16=WGT, c17=DEN)
#define SB_WB1    28688    // w_in^T   [64n][32k] fp16, stride 80B
#define SB_WB2    33808    // w_out^T  [16n][64k] fp16, stride 144B
#define SB_WB3    36112    // rgb_w1^T [64n][16k] fp16, stride 48B
#define SB_WB4    39184    // rgb_w2^T [64n][64k] fp16, stride 144B
#define SMEM_BYTES 48400

__device__ __forceinline__ u32 smem_u32(const void* p) {
    u32 a;
    asm("{ .reg .u64 t; cvta.to.shared.u64 t, %1; cvt.u32.u64 %0, t; }"
        : "=r"(a) : "l"(p));
    return a;
}
__device__ __forceinline__ void ldsm_x4(u32 a[4], u32 addr) {
    asm volatile("ldmatrix.sync.aligned.m8n8.x4.shared.b16 {%0,%1,%2,%3}, [%4];"
                 : "=r"(a[0]), "=r"(a[1]), "=r"(a[2]), "=r"(a[3]) : "r"(addr));
}
__device__ __forceinline__ void ldsm_x2(u32 b[2], u32 addr) {
    asm volatile("ldmatrix.sync.aligned.m8n8.x2.shared.b16 {%0,%1}, [%2];"
                 : "=r"(b[0]), "=r"(b[1]) : "r"(addr));
}
__device__ __forceinline__ void mma16816(float d[4], const u32 a[4], const u32 b[2]) {
    asm volatile("mma.sync.aligned.m16n8k16.row.col.f32.f16.f16.f32 "
                 "{%0,%1,%2,%3},{%4,%5,%6,%7},{%8,%9},{%0,%1,%2,%3};"
                 : "+f"(d[0]), "+f"(d[1]), "+f"(d[2]), "+f"(d[3])
                 : "r"(a[0]), "r"(a[1]), "r"(a[2]), "r"(a[3]),
                   "r"(b[0]), "r"(b[1]));
}

// A fragment addresses (row-major ACT, stride 144B)
__device__ __forceinline__ u32 a_addr(u32 actb, int R, int mt, int ks, int lane) {
    const int sub = lane >> 3, r = lane & 7;
    return actb + (u32)((R + mt * 16 + ((sub & 1) << 3) + r) * 144
                        + ks * 32 + ((sub >> 1) << 4));
}
// B fragment addresses (col-major B == w^T stored [n][k], k-contiguous)
__device__ __forceinline__ u32 b_addr(u32 wb, int strideB, int nt, int ks, int lane) {
    const int sub = (lane >> 3) & 1, r = lane & 7;
    return wb + (u32)((nt * 8 + r) * strideB + ks * 32 + (sub << 4));
}

__device__ __forceinline__ void level_fetch(
    float px, float py, float pz, float r,
    const float2* __restrict__ tab,
    float2 tv[8], float& ax, float& ay, float& az)
{
    const float X = px * r, Y = py * r, Z = pz * r;
    const float fx = floorf(X), fy = floorf(Y), fz = floorf(Z);
    ax = X - fx; ay = Y - fy; az = Z - fz;
    const u32 ix = (u32)fx, iy = (u32)fy, iz = (u32)fz;
    const u32 hx0 = ix, hx1 = ix + 1u;
    const u32 hy0 = iy * 2654435761u, hy1 = hy0 + 2654435761u;
    const u32 hz0 = iz * 805459861u,  hz1 = hz0 + 805459861u;
    #pragma unroll
    for (int c = 0; c < 8; c++) {
        const u32 hx = (c & 4) ? hx1 : hx0;
        const u32 hy = (c & 2) ? hy1 : hy0;
        const u32 hz = (c & 1) ? hz1 : hz0;
        tv[c] = __ldg(tab + ((hx ^ hy ^ hz) & HMASK));
    }
}

__global__ void __launch_bounds__(128, 4) fused_hmma_kernel(
    const float* __restrict__ xyz, const float* __restrict__ delta,
    const float* __restrict__ table,
    const float* __restrict__ w_in, const float* __restrict__ w_out,
    const float* __restrict__ rw1, const float* __restrict__ rw2,
    const float* __restrict__ rw3, float4* __restrict__ out, Consts cc,
    float offset)
{
    extern __shared__ char smem[];
    float* dsf = (float*)smem;
    const u32 sbase = smem_u32(smem);
    const u32 actb = sbase + SB_ACT;
    const int t = threadIdx.x;
    const int lane = t & 31, wid = t >> 5;
    const int g = lane >> 2, t4 = lane & 3;
    const int R = wid * 32;

    // ---------------- prologue: stage fp16 transposed weights ----------------
    {
        half* wb1 = (half*)(smem + SB_WB1);
        half* wb2 = (half*)(smem + SB_WB2);
        half* wb3 = (half*)(smem + SB_WB3);
        half* wb4 = (half*)(smem + SB_WB4);
        for (int i = t; i < 64 * 32; i += 128) {          // WB1[n][k] = w_in[k][n]
            const int n = i >> 5, k = i & 31;
            wb1[n * 40 + k] = __float2half_rn(w_in[k * 64 + n]);
        }
        for (int i = t; i < 16 * 64; i += 128) {          // WB2[n][k] = w_out[k][n]
            const int n = i >> 6, k = i & 63;
            wb2[n * 72 + k] = __float2half_rn(w_out[k * 16 + n]);
        }
        for (int i = t; i < 64 * 16; i += 128) {          // WB3[n][k] = rgb_w1[k][n], k15=0
            const int n = i >> 4, k = i & 15;
            wb3[n * 24 + k] = (k < 15) ? __float2half_rn(rw1[k * 64 + n]) : __half(0.f);
        }
        for (int i = t; i < 64 * 64; i += 128) {          // WB4[n][k] = rgb_w2[k][n]
            const int n = i >> 6, k = i & 63;
            wb4[n * 72 + k] = __float2half_rn(rw2[k * 64 + n]);
        }
        if (t < 64) {
            #pragma unroll
            for (int c = 0; c < 3; c++)
                dsf[SB_W3T / 4 + c * 64 + t] = rw3[t * 3 + c];   // w3^T [c][n]
            dsf[SB_WOUT0 / 4 + t] = w_out[t * 16];               // w_out col 0 (fp32)
        }
    }
    __syncthreads();

    // ------ phase 1: encode point t -> ACT row t (fp16), 2-level lookahead ---
    const int p = blockIdx.x * 128 + t;
    {
        const float px = __ldg(xyz + 3 * p);
        const float py = __ldg(xyz + 3 * p + 1);
        const float pz = __ldg(xyz + 3 * p + 2);
        float2 tvb[3][8];
        float fr[3][3];
        level_fetch(px, py, pz, cc.res[0], (const float2*)table,
                    tvb[0], fr[0][0], fr[0][1], fr[0][2]);
        level_fetch(px, py, pz, cc.res[1], (const float2*)table + HSIZE,
                    tvb[1], fr[1][0], fr[1][1], fr[1][2]);
        #pragma unroll
        for (int l = 0; l < NLEV; l++) {
            const int cur = l % 3, pf = (l + 2) % 3;
            if (l + 2 < NLEV)
                level_fetch(px, py, pz, cc.res[l + 2],
                            (const float2*)table + (size_t)(l + 2) * HSIZE,
                            tvb[pf], fr[pf][0], fr[pf][1], fr[pf][2]);
            const float ax = fr[cur][0], ay = fr[cur][1], az = fr[cur][2];
            const float bx = 1.f - ax, by = 1.f - ay, bz = 1.f - az;
            float a0 = 0.f, a1 = 0.f;
            #pragma unroll
            for (int c = 0; c < 8; c++) {
                const float w = ((c & 4) ? ax : bx) * ((c & 2) ? ay : by) * ((c & 1) ? az : bz);
                a0 = fmaf(w, tvb[cur][c].x, a0);
                a1 = fmaf(w, tvb[cur][c].y, a1);
            }
            __half2 hv = __floats2half2_rn(a0, a1);
            *(u32*)(smem + SB_ACT + t * 144 + l * 4) = *(u32*)&hv;
        }
    }
    __syncwarp();   // warp w's rows [R,R+32) now complete for warp-private GEMMs

    // ---------------- GEMM1: h = enc @ w_in  (M32/warp, N64, K32) -----------
    float accH[2][8][4];
    #pragma unroll
    for (int i = 0; i < 2; i++)
        #pragma unroll
        for (int j = 0; j < 8; j++)
            #pragma unroll
            for (int q = 0; q < 4; q++) accH[i][j][q] = 0.f;
    #pragma unroll
    for (int ks = 0; ks < 2; ks++) {
        u32 a0[4], a1[4];
        ldsm_x4(a0, a_addr(actb, R, 0, ks, lane));
        ldsm_x4(a1, a_addr(actb, R, 1, ks, lane));
        #pragma unroll
        for (int nt = 0; nt < 8; nt++) {
            u32 b[2];
            ldsm_x2(b, b_addr(sbase + SB_WB1, 80, nt, ks, lane));
            mma16816(accH[0][nt], a0, b);
            mma16816(accH[1][nt], a1, b);
        }
    }

    // density (raw col 0) scalar fp32 from h fragments + w_out col 0
    {
        float pd[2][2] = {{0.f, 0.f}, {0.f, 0.f}};
        #pragma unroll
        for (int mt = 0; mt < 2; mt++)
            #pragma unroll
            for (int nt = 0; nt < 8; nt++) {
                const int c0 = nt * 8 + 2 * t4;
                const float w0 = dsf[SB_WOUT0 / 4 + c0];
                const float w1 = dsf[SB_WOUT0 / 4 + c0 + 1];
                pd[mt][0] += fmaxf(accH[mt][nt][0], 0.f) * w0 + fmaxf(accH[mt][nt][1], 0.f) * w1;
                pd[mt][1] += fmaxf(accH[mt][nt][2], 0.f) * w0 + fmaxf(accH[mt][nt][3], 0.f) * w1;
            }
        #pragma unroll
        for (int mt = 0; mt < 2; mt++)
            #pragma unroll
            for (int j = 0; j < 2; j++) {
                pd[mt][j] += __shfl_xor_sync(0xffffffffu, pd[mt][j], 1);
                pd[mt][j] += __shfl_xor_sync(0xffffffffu, pd[mt][j], 2);
            }
        if (t4 == 0) {
            #pragma unroll
            for (int mt = 0; mt < 2; mt++) {
                const int row = R + mt * 16 + g;
                dsf[SB_RAW / 4 + row * 18 + 17] = pd[mt][0];
                dsf[SB_RAW / 4 + (row + 8) * 18 + 17] = pd[mt][1];
            }
        }
    }

    // relu(h) -> fp16 -> ACT (cols 0..63)
    #pragma unroll
    for (int mt = 0; mt < 2; mt++)
        #pragma unroll
        for (int nt = 0; nt < 8; nt++) {
            const int row = R + mt * 16 + g;
            const int cb = (nt * 8 + 2 * t4) * 2;
            __half2 x = __floats2half2_rn(fmaxf(accH[mt][nt][0], 0.f),
                                          fmaxf(accH[mt][nt][1], 0.f));
            *(u32*)(smem + SB_ACT + row * 144 + cb) = *(u32*)&x;
            __half2 y = __floats2half2_rn(fmaxf(accH[mt][nt][2], 0.f),
                                          fmaxf(accH[mt][nt][3], 0.f));
            *(u32*)(smem + SB_ACT + (row + 8) * 144 + cb) = *(u32*)&y;
        }
    __syncwarp();

    // ---------------- GEMM2: raw = relu(h) @ w_out  (N16, K64) --------------
    {
        float acc2[2][2][4];
        #pragma unroll
        for (int i = 0; i < 2; i++)
            #pragma unroll
            for (int j = 0; j < 2; j++)
                #pragma unroll
                for (int q = 0; q < 4; q++) acc2[i][j][q] = 0.f;
        #pragma unroll
        for (int ks = 0; ks < 4; ks++) {
            u32 a0[4], a1[4];
            ldsm_x4(a0, a_addr(actb, R, 0, ks, lane));
            ldsm_x4(a1, a_addr(actb, R, 1, ks, lane));
            #pragma unroll
            for (int nt = 0; nt < 2; nt++) {
                u32 b[2];
                ldsm_x2(b, b_addr(sbase + SB_WB2, 144, nt, ks, lane));
                mma16816(acc2[0][nt], a0, b);
                mma16816(acc2[1][nt], a1, b);
            }
        }
        // store raw to RAW (fp32)
        #pragma unroll
        for (int mt = 0; mt < 2; mt++)
            #pragma unroll
            for (int nt = 0; nt < 2; nt++) {
                const int row = R + mt * 16 + g;
                const int c = nt * 8 + 2 * t4;
                *(float2*)&dsf[SB_RAW / 4 + row * 18 + c] =
                    make_float2(acc2[mt][nt][0], acc2[mt][nt][1]);
                *(float2*)&dsf[SB_RAW / 4 + (row + 8) * 18 + c] =
                    make_float2(acc2[mt][nt][2], acc2[mt][nt][3]);
            }
    }
    __syncwarp();

    // feats (raw[1..15]) -> fp16 ACT row t cols 0..15 (k15 = 0)
    {
        const float* rr = dsf + SB_RAW / 4 + t * 18;
        #pragma unroll
        for (int j = 0; j < 8; j++) {
            const float lo = rr[2 * j + 1];
            const float hi = (j < 7) ? rr[2 * j + 2] : 0.f;
            __half2 hv = __floats2half2_rn(lo, hi);
            *(u32*)(smem + SB_ACT + t * 144 + j * 4) = *(u32*)&hv;
        }
    }

    // ---------------- volrend: block scan over density -----------------------
    {
        const float d0raw = dsf[SB_RAW / 4 + t * 18 + 17];
        const float dd = expf(d0raw + offset + logf(__ldg(delta + p)));
        float s = dd;
        #pragma unroll
        for (int o = 1; o < 32; o <<= 1) {
            const float v = __shfl_up_sync(0xffffffffu, s, o);
            if (lane >= o) s += v;
        }
        if (lane == 31) dsf[SB_WSUM / 4 + wid] = s;
        __syncthreads();
        float pref = 0.f;
        #pragma unroll
        for (int w = 0; w < 3; w++)
            if (wid > w) pref += dsf[SB_WSUM / 4 + w];
        const float wgt = (1.f - expf(-dd)) * expf(-(pref + s - dd));
        dsf[SB_RAW / 4 + t * 18 + 16] = wgt;
    }
    __syncwarp();

    // ---------------- GEMM3: h1 = feats @ rgb_w1  (N64, K16) ----------------
    #pragma unroll
    for (int i = 0; i < 2; i++)
        #pragma unroll
        for (int j = 0; j < 8; j++)
            #pragma unroll
            for (int q = 0; q < 4; q++) accH[i][j][q] = 0.f;
    {
        u32 a0[4], a1[4];
        ldsm_x4(a0, a_addr(actb, R, 0, 0, lane));
        ldsm_x4(a1, a_addr(actb, R, 1, 0, lane));
        #pragma unroll
        for (int nt = 0; nt < 8; nt++) {
            u32 b[2];
            ldsm_x2(b, b_addr(sbase + SB_WB3, 48, nt, 0, lane));
            mma16816(accH[0][nt], a0, b);
            mma16816(accH[1][nt], a1, b);
        }
    }
    // relu(h1) -> fp16 -> ACT cols 0..63
    #pragma unroll
    for (int mt = 0; mt < 2; mt++)
        #pragma unroll
        for (int nt = 0; nt < 8; nt++) {
            const int row = R + mt * 16 + g;
            const int cb = (nt * 8 + 2 * t4) * 2;
            __half2 x = __floats2half2_rn(fmaxf(accH[mt][nt][0], 0.f),
                                          fmaxf(accH[mt][nt][1], 0.f));
            *(u32*)(smem + SB_ACT + row * 144 + cb) = *(u32*)&x;
            __half2 y = __floats2half2_rn(fmaxf(accH[mt][nt][2], 0.f),
                                          fmaxf(accH[mt][nt][3], 0.f));
            *(u32*)(smem + SB_ACT + (row + 8) * 144 + cb) = *(u32*)&y;
        }
    __syncwarp();

    // ---------------- GEMM4: h2 = relu(h1) @ rgb_w2  (N64, K64) -------------
    #pragma unroll
    for (int i = 0; i < 2; i++)
        #pragma unroll
        for (int j = 0; j < 8; j++)
            #pragma unroll
            for (int q = 0; q < 4; q++) accH[i][j][q] = 0.f;
    #pragma unroll
    for (int ks = 0; ks < 4; ks++) {
        u32 a0[4], a1[4];
        ldsm_x4(a0, a_addr(actb, R, 0, ks, lane));
        ldsm_x4(a1, a_addr(actb, R, 1, ks, lane));
        #pragma unroll
        for (int nt = 0; nt < 8; nt++) {
            u32 b[2];
            ldsm_x2(b, b_addr(sbase + SB_WB4, 144, nt, ks, lane));
            mma16816(accH[0][nt], a0, b);
            mma16816(accH[1][nt], a1, b);
        }
    }

    // ---------------- rgb = sigmoid(relu(h2) @ rgb_w3) -----------------------
    #pragma unroll
    for (int mt = 0; mt < 2; mt++) {
        float pr0[3] = {0.f, 0.f, 0.f};   // row R+mt*16+g
        float pr1[3] = {0.f, 0.f, 0.f};   // row +8
        #pragma unroll
        for (int nt = 0; nt < 8; nt++) {
            const int c0 = nt * 8 + 2 * t4;
            const float v0 = fmaxf(accH[mt][nt][0], 0.f);
            const float v1 = fmaxf(accH[mt][nt][1], 0.f);
            const float v2 = fmaxf(accH[mt][nt][2], 0.f);
            const float v3 = fmaxf(accH[mt][nt][3], 0.f);
            #pragma unroll
            for (int c = 0; c < 3; c++) {
                const float2 wv = *(const float2*)&dsf[SB_W3T / 4 + c * 64 + c0];
                pr0[c] += v0 * wv.x + v1 * wv.y;
                pr1[c] += v2 * wv.x + v3 * wv.y;
            }
        }
        #pragma unroll
        for (int c = 0; c < 3; c++) {
            pr0[c] += __shfl_xor_sync(0xffffffffu, pr0[c], 1);
            pr0[c] += __shfl_xor_sync(0xffffffffu, pr0[c], 2);
            pr1[c] += __shfl_xor_sync(0xffffffffu, pr1[c], 1);
            pr1[c] += __shfl_xor_sync(0xffffffffu, pr1[c], 2);
        }
        if (t4 == 0) {
            const int row0 = R + mt * 16 + g;
            const float wg0 = dsf[SB_RAW / 4 + row0 * 18 + 16];
            out[blockIdx.x * 128 + row0] = make_float4(
                wg0, 1.f / (1.f + expf(-pr0[0])),
                1.f / (1.f + expf(-pr0[1])), 1.f / (1.f + expf(-pr0[2])));
            const int row1 = row0 + 8;
            const float wg1 = dsf[SB_RAW / 4 + row1 * 18 + 16];
            out[blockIdx.x * 128 + row1] = make_float4(
                wg1, 1.f / (1.f + expf(-pr1[0])),
                1.f / (1.f + expf(-pr1[1])), 1.f / (1.f + expf(-pr1[2])));
        }
    }
}

extern "C" void kernel_launch(void* const* d_in, const int* in_sizes, int n_in,
                              void* d_out, int out_size)
{
    const float* xyz   = (const float*)d_in[0];
    const float* delta = (const float*)d_in[1];
    const float* table = (const float*)d_in[2];
    const float* w_in  = (const float*)d_in[3];
    const float* w_out = (const float*)d_in[4];
    const float* rw1   = (const float*)d_in[5];
    const float* rw2   = (const float*)d_in[6];
    const float* rw3   = (const float*)d_in[7];
    float4* out = (float4*)d_out;

    Consts cc;
    const double scale = exp((log(4096.0) - log(16.0)) / 15.0);
    for (int l = 0; l < NLEV; l++)
        cc.res[l] = (float)floor(16.0 * pow(scale, (double)l));
    const float offset = (float)(log(log(1.0 / 0.99)) - log(6.0 - 2.0) - 0.5);

    static int inited = 0;
    if (!inited) {
        cudaFuncSetAttribute(fused_hmma_kernel,
                             cudaFuncAttributeMaxDynamicSharedMemorySize,
                             SMEM_BYTES);
        inited = 1;
    }

    fused_hmma_kernel<<<4096, 128, SMEM_BYTES>>>(
        xyz, delta, table, w_in, w_out, rw1, rw2, rw3, out, cc, offset);
}